// round 17
// baseline (speedup 1.0000x reference)
#include <cuda_runtime.h>
#include <cuda_fp16.h>
#include <math.h>
#include <stdint.h>

// ---- problem constants ----
#define BSX 4096   // B*S
#define BB  2
#define SEQ 2048
#define EMB 768
#define TT  128
#define NH  12
#define DHD 64
#define FF  3072
#define KNN 16
#define CATW (EMB + TT)   // 896
#define QKVW (3 * EMB)    // 2304

// ---- fp32 scratch ----
__device__ float g_topo[BSX * TT];
__device__ float g_tt[BSX * TT];
__device__ float g_h1[BSX * EMB];

// ---- fp16 scratch ----
__device__ __half g_disth[(long long)BB * SEQ * SEQ];   // 16.7 MB fp16
__device__ __half g_hh[BSX * EMB];
__device__ __half g_hnh[BSX * EMB];
__device__ __half g_xh[BSX * EMB];
__device__ __half g_combh[BSX * TT];
__device__ __half g_tmp256h[BSX * 256];
__device__ __half g_tth[BSX * TT];
__device__ __half g_qkvh[(long long)BSX * QKVW];
__device__ __half g_cath[BSX * CATW];
__device__ __half g_ctxh[BSX * EMB];
__device__ __half g_yh[BSX * EMB];
__device__ __half g_ffh[(long long)BSX * FF];

// ---- transposed fp16 weights [N][K] ----
__device__ __half g_wt_topo[TT * EMB];
__device__ __half g_wt_m1[256 * TT];
__device__ __half g_wt_m2[TT * 256];
__device__ __half g_wt_p1[TT * TT];
__device__ __half g_wt_p2[TT * TT];
__device__ __half g_wt_qkv[QKVW * EMB];
__device__ __half g_wt_gate[EMB * CATW];
__device__ __half g_wt_o[EMB * EMB];
__device__ __half g_wt_f1[FF * EMB];
__device__ __half g_wt_f2[EMB * FF];

__device__ __forceinline__ void mma_f16(float* c, const uint32_t* a, uint32_t b0, uint32_t b1) {
    asm volatile(
        "mma.sync.aligned.m16n8k16.row.col.f32.f16.f16.f32 "
        "{%0,%1,%2,%3},{%4,%5,%6,%7},{%8,%9},{%0,%1,%2,%3};"
        : "+f"(c[0]), "+f"(c[1]), "+f"(c[2]), "+f"(c[3])
        : "r"(a[0]), "r"(a[1]), "r"(a[2]), "r"(a[3]), "r"(b0), "r"(b1));
}

__device__ __forceinline__ void cpa16(void* s, const void* g) {
    unsigned sa = (unsigned)__cvta_generic_to_shared(s);
    asm volatile("cp.async.cg.shared.global [%0], [%1], 16;" :: "r"(sa), "l"(g));
}
__device__ __forceinline__ void cpa_commit() { asm volatile("cp.async.commit_group;"); }
__device__ __forceinline__ void cpa_wait1()  { asm volatile("cp.async.wait_group 1;"); }
__device__ __forceinline__ void cpa_wait0()  { asm volatile("cp.async.wait_group 0;"); }

__device__ __forceinline__ void ldsm4(uint32_t* r, uint32_t addr) {
    asm volatile("ldmatrix.sync.aligned.m8n8.x4.shared.b16 {%0,%1,%2,%3}, [%4];"
                 : "=r"(r[0]), "=r"(r[1]), "=r"(r[2]), "=r"(r[3]) : "r"(addr));
}

__device__ __forceinline__ void ldsm4t(uint32_t* r, uint32_t addr) {
    asm volatile("ldmatrix.sync.aligned.m8n8.x4.trans.shared.b16 {%0,%1,%2,%3}, [%4];"
                 : "=r"(r[0]), "=r"(r[1]), "=r"(r[2]), "=r"(r[3]) : "r"(addr));
}

__device__ __forceinline__ uint32_t h2ex2(uint32_t x) {
    uint32_t y;
    asm("ex2.approx.f16x2 %0, %1;" : "=r"(y) : "r"(x));
    return y;
}

// ============================================================================
// fp16 tensor-core GEMM (m16n8k16), cp.async 3-stage k32 pipeline, ldmatrix.
// SYM=1: C symmetric (A==B, M==N): upper-triangle tiles only + mirror store.
// ============================================================================
#define HSTG (128 * 40)
#define HG_SMEM (3 * HSTG * 2 * 2)

template<int ACT, int CH, int RH, int R2H, int SYM>
__global__ void __launch_bounds__(256) hgemm(
    const __half* __restrict__ A, const __half* __restrict__ B,
    void* __restrict__ Cv, const float* __restrict__ bias,
    const void* __restrict__ resv, const void* __restrict__ res2v,
    int K, int lda, int ldb, int ldc, int ldr1, int ldr2,
    int zdiv, long long sA1, long long sA2,
    long long sB1, long long sB2, long long sC1, long long sC2)
{
    if (SYM && blockIdx.x < blockIdx.y) return;

    extern __shared__ __half hs[];
    __half* As = hs;
    __half* Bs = hs + 3 * HSTG;

    int z = blockIdx.z;
    long long zm = z % zdiv, zd = z / zdiv;
    A += zm * sA1 + zd * sA2;
    B += zm * sB1 + zd * sB2;
    long long co = zm * sC1 + zd * sC2;

    const int t    = threadIdx.x;
    const int lane = t & 31;
    const int wid  = t >> 5;
    const int lr   = lane >> 2;
    const int lc   = lane & 3;
    const int wm   = (wid & 3) * 32;
    const int wn   = (wid >> 2) * 64;
    const int bm   = blockIdx.y * 128;
    const int bn   = blockIdx.x * 128;

    const uint32_t sbase = (uint32_t)__cvta_generic_to_shared(hs);
    const uint32_t offA = (uint32_t)((lane & 15) * 80 + (lane >> 4) * 16);
    const uint32_t offB = (uint32_t)((((lane >> 4) & 1) * 8 + (lane & 7)) * 80 + ((lane >> 3) & 1) * 16);

    float acc[2][8][4];
    #pragma unroll
    for (int mt = 0; mt < 2; mt++)
        #pragma unroll
        for (int nt = 0; nt < 8; nt++)
            #pragma unroll
            for (int i = 0; i < 4; i++) acc[mt][nt][i] = 0.f;

    auto issue = [&](int buf, int k0) {
        #pragma unroll
        for (int i = 0; i < 2; i++) {
            int c = t + i * 256;
            int row = c >> 2, kq = (c & 3) * 8;
            cpa16(&As[buf * HSTG + row * 40 + kq],
                  A + (long long)(bm + row) * lda + k0 + kq);
        }
        #pragma unroll
        for (int i = 0; i < 2; i++) {
            int c = t + i * 256;
            int row = c >> 2, kq = (c & 3) * 8;
            cpa16(&Bs[buf * HSTG + row * 40 + kq],
                  B + (long long)(bn + row) * ldb + k0 + kq);
        }
        cpa_commit();
    };

    const int iters = K >> 5;
    issue(0, 0);
    issue(1, 32);

    for (int kb = 0; kb < iters; kb++) {
        cpa_wait1();
        __syncthreads();
        int cur = kb - (kb / 3) * 3;
        uint32_t aB = sbase + (uint32_t)cur * (HSTG * 2);
        uint32_t bB = sbase + (uint32_t)(3 + cur) * (HSTG * 2);

        #pragma unroll
        for (int kk = 0; kk < 2; kk++) {
            uint32_t af[2][4];
            #pragma unroll
            for (int mt = 0; mt < 2; mt++)
                ldsm4(af[mt], aB + (wm + mt * 16) * 80 + kk * 32 + offA);

            #pragma unroll
            for (int p = 0; p < 4; p++) {
                uint32_t bb[4];
                ldsm4(bb, bB + (wn + p * 16) * 80 + kk * 32 + offB);
                #pragma unroll
                for (int sub = 0; sub < 2; sub++)
                    #pragma unroll
                    for (int mt = 0; mt < 2; mt++)
                        mma_f16(acc[mt][p * 2 + sub], af[mt], bb[sub * 2], bb[sub * 2 + 1]);
            }
        }

        int nst  = kb + 2;
        int nbuf = nst - (nst / 3) * 3;
        int nk0  = (nst < iters ? nst : iters - 1) << 5;
        issue(nbuf, nk0);
    }

    const float* res = (const float*)resv;
    const __half* resh = (const __half*)resv;
    #pragma unroll
    for (int mt = 0; mt < 2; mt++) {
        #pragma unroll
        for (int nt = 0; nt < 8; nt++) {
            int mrow = bm + wm + mt * 16 + lr;
            int ncol = bn + wn + nt * 8 + 2 * lc;
            #pragma unroll
            for (int half_ = 0; half_ < 2; half_++) {
                int m = mrow + half_ * 8;
                float v0 = acc[mt][nt][half_ * 2 + 0];
                float v1 = acc[mt][nt][half_ * 2 + 1];
                if (bias) { v0 += bias[ncol]; v1 += bias[ncol + 1]; }
                if (ACT == 1) { v0 = fmaxf(v0, 0.f); v1 = fmaxf(v1, 0.f); }
                if (ACT == 2) {
                    float u = v0;
                    float tt2 = 1.5957691216057308f * (u + 0.044715f * u * u * u);
                    v0 = u / (1.f + __expf(-tt2));
                    u = v1;
                    tt2 = 1.5957691216057308f * (u + 0.044715f * u * u * u);
                    v1 = u / (1.f + __expf(-tt2));
                }
                long long off = (long long)m * ldc + ncol + co;
                if (ACT == 3) {
                    float s0 = 1.f / (1.f + __expf(-v0));
                    float s1 = 1.f / (1.f + __expf(-v1));
                    long long o1 = (long long)m * ldr1 + ncol;
                    long long o2 = (long long)m * ldr2 + ncol;
                    float r1x, r1y, r2x, r2y;
                    if (RH) {
                        __half2 rh = *(const __half2*)(resh + o1);
                        r1x = __half2float(rh.x); r1y = __half2float(rh.y);
                    } else {
                        float2 r1 = *(const float2*)(res + o1);
                        r1x = r1.x; r1y = r1.y;
                    }
                    if (R2H) {
                        __half2 rh2 = *(const __half2*)((const __half*)res2v + o2);
                        r2x = __half2float(rh2.x); r2y = __half2float(rh2.y);
                    } else {
                        float2 r2 = *(const float2*)((const float*)res2v + o2);
                        r2x = r2.x; r2y = r2.y;
                    }
                    v0 = s0 * r1x + (1.f - s0) * r2x;
                    v1 = s1 * r1y + (1.f - s1) * r2y;
                } else if (resv) {
                    float2 r1 = *(const float2*)(res + (long long)m * ldr1 + ncol + co);
                    v0 += r1.x; v1 += r1.y;
                }
                if (CH) {
                    __half h0 = __float2half(v0), h1v = __float2half(v1);
                    __half2 hv; hv.x = h0; hv.y = h1v;
                    *(__half2*)((__half*)Cv + off) = hv;
                    if (SYM && blockIdx.x != blockIdx.y) {
                        ((__half*)Cv)[(long long)ncol * ldc + m + co]       = h0;
                        ((__half*)Cv)[(long long)(ncol + 1) * ldc + m + co] = h1v;
                    }
                } else {
                    float2 o2v = {v0, v1};
                    *(float2*)((float*)Cv + off) = o2v;
                    if (SYM && blockIdx.x != blockIdx.y) {
                        ((float*)Cv)[(long long)ncol * ldc + m + co]       = v0;
                        ((float*)Cv)[(long long)(ncol + 1) * ldc + m + co] = v1;
                    }
                }
            }
        }
    }
}

// ============================================================================
// Flash attention fp16 over fused qkv buffer, z0 offset for batch-split launch.
// ============================================================================
#define FS_P 0
#define FS_K 17408
#define FS_V 35840
#define FS_TOT_BYTES 108544
#define LOG2E 1.4426950408889634f

__global__ void __launch_bounds__(256) flash_k(
    const __half* __restrict__ qkv, const int* __restrict__ mask,
    __half* __restrict__ outc, int z0)
{
    extern __shared__ __half fh[];
    __half* sP = fh + FS_P;
    __half* sK = fh + FS_K;
    __half* sV = fh + FS_V;

    const int t = threadIdx.x, lane = t & 31, w = t >> 5;
    const int lr = lane >> 2, lc = lane & 3;
    const int z = blockIdx.y + z0, b = z / NH, hh = z % NH;
    const int bm = blockIdx.x * 128;
    const long long base = (long long)b * SEQ * QKVW + hh * DHD;
    const __half* qp = qkv + base;
    const __half* kp = qkv + base + EMB;
    const __half* vp = qkv + base + 2 * EMB;
    const int* mrow = mask + b * SEQ;

    const uint32_t fbase = (uint32_t)__cvta_generic_to_shared(fh);
    const uint32_t pbase = fbase;
    const uint32_t kbase = fbase + FS_K * 2;
    const uint32_t vbase = fbase + FS_V * 2;
    const uint32_t offK = (uint32_t)((((lane >> 4) & 1) * 8 + (lane & 7)) * 144 + ((lane >> 3) & 1) * 16);
    const uint32_t offP = (uint32_t)((lane & 15) * 272 + (lane >> 4) * 16);
    const uint32_t offV = (uint32_t)((lane & 15) * 144 + (lane >> 4) * 16);

    #pragma unroll
    for (int j = 0; j < 4; j++) {
        int flat = t + j * 256;
        int row = flat >> 3, q8 = (flat & 7) << 3;
        cpa16(&sP[row * 136 + q8], qp + (long long)(bm + row) * QKVW + q8);
    }
    cpa_commit();

    auto issueKV = [&](int kt) {
        int buf = kt & 1;
        #pragma unroll
        for (int j = 0; j < 4; j++) {
            int flat = t + j * 256;
            int row = flat >> 3, q8 = (flat & 7) << 3;
            cpa16(&sK[buf * 9216 + row * 72 + q8],
                  kp + (long long)(kt * 128 + row) * QKVW + q8);
        }
        #pragma unroll
        for (int j = 0; j < 4; j++) {
            int flat = t + j * 256;
            int row = flat >> 3, q8 = (flat & 7) << 3;
            cpa16(&sV[buf * 9216 + row * 72 + q8],
                  vp + (long long)(kt * 128 + row) * QKVW + q8);
        }
        cpa_commit();
    };
    issueKV(0);

    cpa_wait1();
    __syncthreads();

    const int wq = w * 16;
    uint32_t qf[4][4];
    #pragma unroll
    for (int ks = 0; ks < 4; ks++)
        ldsm4(qf[ks], pbase + (uint32_t)wq * 272 + ks * 32 + offP);
    __syncthreads();

    float ctx[8][4];
    #pragma unroll
    for (int nt = 0; nt < 8; nt++)
        #pragma unroll
        for (int i = 0; i < 4; i++) ctx[nt][i] = 0.f;
    float m0 = -1e30f, m1 = -1e30f, l0 = 0.f, l1 = 0.f;

    for (int kt = 0; kt < 16; kt++) {
        cpa_wait0();
        __syncthreads();
        if (kt + 1 < 16) issueKV(kt + 1);

        const int buf = kt & 1;
        const uint32_t kB = kbase + (uint32_t)buf * (9216 * 2);
        const uint32_t vB = vbase + (uint32_t)buf * (9216 * 2);

        float S[16][4];
        #pragma unroll
        for (int nt = 0; nt < 16; nt++)
            #pragma unroll
            for (int i = 0; i < 4; i++) S[nt][i] = 0.f;
        #pragma unroll
        for (int ks = 0; ks < 4; ks++) {
            #pragma unroll
            for (int p = 0; p < 8; p++) {
                uint32_t bb[4];
                ldsm4(bb, kB + (uint32_t)(p * 16) * 144 + ks * 32 + offK);
                mma_f16(S[p * 2],     qf[ks], bb[0], bb[1]);
                mma_f16(S[p * 2 + 1], qf[ks], bb[2], bb[3]);
            }
        }

        float nm0 = -1e30f, nm1 = -1e30f;
        #pragma unroll
        for (int nt = 0; nt < 16; nt++) {
            int c0 = kt * 128 + nt * 8 + 2 * lc;
            int2 mg = *(const int2*)&mrow[c0];
            float s0 = S[nt][0] * 0.125f, s1 = S[nt][1] * 0.125f;
            float s2 = S[nt][2] * 0.125f, s3 = S[nt][3] * 0.125f;
            if (mg.x == 0) { s0 = -10000.f; s2 = -10000.f; }
            if (mg.y == 0) { s1 = -10000.f; s3 = -10000.f; }
            S[nt][0] = s0; S[nt][1] = s1; S[nt][2] = s2; S[nt][3] = s3;
            nm0 = fmaxf(nm0, fmaxf(s0, s1));
            nm1 = fmaxf(nm1, fmaxf(s2, s3));
        }
        nm0 = fmaxf(nm0, __shfl_xor_sync(0xffffffffu, nm0, 1));
        nm0 = fmaxf(nm0, __shfl_xor_sync(0xffffffffu, nm0, 2));
        nm1 = fmaxf(nm1, __shfl_xor_sync(0xffffffffu, nm1, 1));
        nm1 = fmaxf(nm1, __shfl_xor_sync(0xffffffffu, nm1, 2));
        float M0 = fmaxf(m0, nm0), M1 = fmaxf(m1, nm1);
        float a0 = expf(m0 - M0), a1 = expf(m1 - M1);

        float r0 = 0.f, r1 = 0.f;
        #pragma unroll
        for (int nt = 0; nt < 16; nt++) {
            __half2 e01 = __floats2half2_rn((S[nt][0] - M0) * LOG2E, (S[nt][1] - M0) * LOG2E);
            __half2 e23 = __floats2half2_rn((S[nt][2] - M1) * LOG2E, (S[nt][3] - M1) * LOG2E);
            uint32_t p01 = h2ex2(*(uint32_t*)&e01);
            uint32_t p23 = h2ex2(*(uint32_t*)&e23);
            float2 f01 = __half22float2(*(__half2*)&p01);
            float2 f23 = __half22float2(*(__half2*)&p23);
            r0 += f01.x + f01.y;
            r1 += f23.x + f23.y;
            *(uint32_t*)(sP + (wq + lr) * 136 + nt * 8 + 2 * lc)     = p01;
            *(uint32_t*)(sP + (wq + lr + 8) * 136 + nt * 8 + 2 * lc) = p23;
        }
        r0 += __shfl_xor_sync(0xffffffffu, r0, 1);
        r0 += __shfl_xor_sync(0xffffffffu, r0, 2);
        r1 += __shfl_xor_sync(0xffffffffu, r1, 1);
        r1 += __shfl_xor_sync(0xffffffffu, r1, 2);
        l0 = l0 * a0 + r0;
        l1 = l1 * a1 + r1;
        m0 = M0; m1 = M1;
        #pragma unroll
        for (int nt = 0; nt < 8; nt++) {
            ctx[nt][0] *= a0; ctx[nt][1] *= a0;
            ctx[nt][2] *= a1; ctx[nt][3] *= a1;
        }
        __syncwarp();

        #pragma unroll
        for (int ks = 0; ks < 8; ks++) {
            uint32_t af[4];
            ldsm4(af, pbase + (uint32_t)wq * 272 + ks * 32 + offP);
            #pragma unroll
            for (int nt = 0; nt < 8; nt += 2) {
                uint32_t bb[4];
                ldsm4t(bb, vB + (uint32_t)(ks * 16) * 144 + (uint32_t)(nt * 16) + offV);
                mma_f16(ctx[nt],     af, bb[0], bb[1]);
                mma_f16(ctx[nt + 1], af, bb[2], bb[3]);
            }
        }
    }

    float il0 = 1.f / l0, il1 = 1.f / l1;
    #pragma unroll
    for (int nt = 0; nt < 8; nt++) {
        long long row0 = (long long)b * SEQ + bm + wq + lr;
        int col = hh * DHD + nt * 8 + 2 * lc;
        *(__half2*)&outc[row0 * CATW + col] = __floats2half2_rn(ctx[nt][0] * il0, ctx[nt][1] * il0);
        *(__half2*)&outc[(row0 + 8) * CATW + col] = __floats2half2_rn(ctx[nt][2] * il1, ctx[nt][3] * il1);
    }
}

// ---- weight transpose + fp32->fp16 ----
__global__ void wt_k(const float* __restrict__ in, __half* __restrict__ out, int K, int N)
{
    __shared__ float tile[32][33];
    int bx = blockIdx.x * 32, by = blockIdx.y * 32;
    int tx = threadIdx.x, ty = threadIdx.y;
    #pragma unroll
    for (int j = ty; j < 32; j += 8)
        tile[j][tx] = in[(long long)(by + j) * N + bx + tx];
    __syncthreads();
    #pragma unroll
    for (int j = ty; j < 32; j += 8)
        out[(long long)(bx + j) * K + by + tx] = __float2half(tile[tx][j]);
}

// ---- fused: hh, hn_h, xh (row-offset for split launch) ----
__global__ void l2ln_k(const float* __restrict__ h,
                       const float* __restrict__ gma, const float* __restrict__ bta, int row0)
{
    int row = blockIdx.x + row0, t = threadIdx.x;
    const float* xr = h + (long long)row * EMB;
    __shared__ float sh[EMB];
    __shared__ float r1[256], r2[256];
    float s = 0.f, ss = 0.f;
    for (int i = t; i < EMB; i += 256) { float v = xr[i]; sh[i] = v; s += v; ss += v * v; }
    r1[t] = s; r2[t] = ss; __syncthreads();
    for (int st = 128; st > 0; st >>= 1) {
        if (t < st) { r1[t] += r1[t + st]; r2[t] += r2[t + st]; }
        __syncthreads();
    }
    float mu   = r1[0] / EMB;
    float var  = r2[0] / EMB - mu * mu;
    float ri   = rsqrtf(var + 1e-6f);
    float invn = 1.f / (sqrtf(r2[0]) + 1e-8f);
    for (int i = t; i < EMB; i += 256) {
        float v = sh[i];
        g_hh [(long long)row * EMB + i] = __float2half(v);
        g_hnh[(long long)row * EMB + i] = __float2half(v * invn);
        g_xh [(long long)row * EMB + i] = __float2half((v - mu) * ri * gma[i] + bta[i]);
    }
}

// ---- single-pass layernorm -> fp16 (values in registers) ----
template<int BLK, int NIT>
__global__ void lnh_k(const float* __restrict__ x, __half* __restrict__ oh,
                      const float* __restrict__ gma, const float* __restrict__ bta, int D)
{
    int row = blockIdx.x, t = threadIdx.x;
    const float* xr = x + (long long)row * D;
    __shared__ float r1[BLK], r2[BLK];
    float xv[NIT];
    float s = 0.f, ss = 0.f;
    #pragma unroll
    for (int i = 0; i < NIT; i++) {
        float v = xr[t + i * BLK];
        xv[i] = v; s += v; ss += v * v;
    }
    r1[t] = s; r2[t] = ss; __syncthreads();
    for (int st = BLK / 2; st > 0; st >>= 1) {
        if (t < st) { r1[t] += r1[t + st]; r2[t] += r2[t + st]; }
        __syncthreads();
    }
    float mu  = r1[0] / D;
    float var = r2[0] / D - mu * mu;
    float ri  = rsqrtf(var + 1e-6f);
    #pragma unroll
    for (int i = 0; i < NIT; i++) {
        int c = t + i * BLK;
        oh[(long long)row * D + c] = __float2half((xv[i] - mu) * ri * gma[c] + bta[c]);
    }
}

// ---- k-NN over fp16 dist (u32 packed keys) + fused combine -> g_combh ----
__global__ void knn_k(int row0)
{
    int row = blockIdx.x + row0;
    int b = row >> 11, i = row & (SEQ - 1);
    const __half* dr = g_disth + (long long)row * SEQ;
    int t = threadIdx.x, lane = t & 31, w = t >> 5;

    __shared__ uint32_t cand[128];
    __shared__ uint32_t fin[KNN];
    __shared__ float    swt[KNN];
    __shared__ int      sidx[KNN];

    uint32_t v[8];
    int base = w * 256;
    #pragma unroll
    for (int r = 0; r < 8; r++) {
        int j = base + r * 32 + lane;
        float d = (j == i) ? 1e9f : (1.f - __half2float(dr[j]));
        v[r] = (__float_as_uint(d) & 0xFFFFF800u) | (unsigned)j;
    }

    #pragma unroll
    for (int it = 0; it < KNN; it++) {
        uint32_t m = v[0];
        #pragma unroll
        for (int r = 1; r < 8; r++) m = min(m, v[r]);
        #pragma unroll
        for (int s = 16; s > 0; s >>= 1)
            m = min(m, __shfl_xor_sync(0xffffffffu, m, s));
        if (lane == 0) cand[w * KNN + it] = m;
        #pragma unroll
        for (int r = 0; r < 8; r++) if (v[r] == m) v[r] = 0xFFFFFFFFu;
    }
    __syncthreads();

    if (w == 0) {
        uint32_t c[4];
        #pragma unroll
        for (int r = 0; r < 4; r++) c[r] = cand[r * 32 + lane];
        #pragma unroll
        for (int it = 0; it < KNN; it++) {
            uint32_t m01 = min(c[0], c[1]);
            uint32_t m23 = min(c[2], c[3]);
            uint32_t m = min(m01, m23);
            #pragma unroll
            for (int s = 16; s > 0; s >>= 1)
                m = min(m, __shfl_xor_sync(0xffffffffu, m, s));
            if (lane == 0) fin[it] = m;
            #pragma unroll
            for (int r = 0; r < 4; r++) if (c[r] == m) c[r] = 0xFFFFFFFFu;
        }
        __syncwarp();
        if (lane < KNN) {
            float d0 = __uint_as_float(fin[0] & 0xFFFFF800u);
            float dk = __uint_as_float(fin[lane] & 0xFFFFF800u);
            float wk = expf(d0 - dk);
            float sum = wk;
            #pragma unroll
            for (int s = 8; s > 0; s >>= 1)
                sum += __shfl_xor_sync(0x0000ffffu, sum, s);
            swt[lane]  = wk / sum;
            sidx[lane] = b * SEQ + (int)(fin[lane] & 0x7FFu);
        }
    }
    __syncthreads();

    if (t < TT) {
        float acc = g_topo[(long long)row * TT + t];
        #pragma unroll
        for (int k2 = 0; k2 < KNN; k2++)
            acc += swt[k2] * g_topo[(long long)sidx[k2] * TT + t];
        g_combh[(long long)row * TT + t] = __float2half(acc);
    }
}

// ============================================================================
extern "C" void kernel_launch(void* const* d_in, const int* in_sizes, int n_in,
                              void* d_out, int out_size)
{
    const float* h      = (const float*)d_in[0];
    const int*   mask   = (const int*)  d_in[1];
    const float* W_topo = (const float*)d_in[2];
    const float* b_topo = (const float*)d_in[3];
    const float* W_m1   = (const float*)d_in[4];
    const float* b_m1   = (const float*)d_in[5];
    const float* W_m2   = (const float*)d_in[6];
    const float* b_m2   = (const float*)d_in[7];
    const float* ln_t_s = (const float*)d_in[8];
    const float* ln_t_b = (const float*)d_in[9];
    const float* W_p1   = (const float*)d_in[10];
    const float* b_p1   = (const float*)d_in[11];
    const float* W_p2   = (const float*)d_in[12];
    const float* b_p2   = (const float*)d_in[13];
    const float* ln1_s  = (const float*)d_in[14];
    const float* ln1_b  = (const float*)d_in[15];
    const float* Wq     = (const float*)d_in[16];
    const float* Wk     = (const float*)d_in[17];
    const float* Wv     = (const float*)d_in[18];
    const float* W_gate = (const float*)d_in[19];
    const float* b_gate = (const float*)d_in[20];
    const float* W_o    = (const float*)d_in[21];
    const float* b_o    = (const float*)d_in[22];
    const float* ln2_s  = (const float*)d_in[23];
    const float* ln2_b  = (const float*)d_in[24];
    const float* W_f1   = (const float*)d_in[25];
    const float* b_f1   = (const float*)d_in[26];
    const float* W_f2   = (const float*)d_in[27];
    const float* b_f2   = (const float*)d_in[28];
    float* out = (float*)d_out;

    float *topo, *tt, *h1;
    __half *disth, *xh, *combh, *tmp256h, *tth, *qkvh, *cath, *ctxh, *yh, *ffh, *hh, *hnh;
    __half *wt_topo, *wt_m1, *wt_m2, *wt_p1, *wt_p2, *wt_qkv, *wt_gate, *wt_o, *wt_f1, *wt_f2;
    cudaGetSymbolAddress((void**)&topo,    g_topo);
    cudaGetSymbolAddress((void**)&tt,      g_tt);
    cudaGetSymbolAddress((void**)&h1,      g_h1);
    cudaGetSymbolAddress((void**)&disth,   g_disth);
    cudaGetSymbolAddress((void**)&hh,      g_hh);
    cudaGetSymbolAddress((void**)&hnh,     g_hnh);
    cudaGetSymbolAddress((void**)&xh,      g_xh);
    cudaGetSymbolAddress((void**)&combh,   g_combh);
    cudaGetSymbolAddress((void**)&tmp256h, g_tmp256h);
    cudaGetSymbolAddress((void**)&tth,     g_tth);
    cudaGetSymbolAddress((void**)&qkvh,    g_qkvh);
    cudaGetSymbolAddress((void**)&cath,    g_cath);
    cudaGetSymbolAddress((void**)&ctxh,    g_ctxh);
    cudaGetSymbolAddress((void**)&yh,      g_yh);
    cudaGetSymbolAddress((void**)&ffh,     g_ffh);
    cudaGetSymbolAddress((void**)&wt_topo, g_wt_topo);
    cudaGetSymbolAddress((void**)&wt_m1,   g_wt_m1);
    cudaGetSymbolAddress((void**)&wt_m2,   g_wt_m2);
    cudaGetSymbolAddress((void**)&wt_p1,   g_wt_p1);
    cudaGetSymbolAddress((void**)&wt_p2,   g_wt_p2);
    cudaGetSymbolAddress((void**)&wt_qkv,  g_wt_qkv);
    cudaGetSymbolAddress((void**)&wt_gate, g_wt_gate);
    cudaGetSymbolAddress((void**)&wt_o,    g_wt_o);
    cudaGetSymbolAddress((void**)&wt_f1,   g_wt_f1);
    cudaGetSymbolAddress((void**)&wt_f2,   g_wt_f2);

    const long long SE = (long long)SEQ * EMB;
    const long long SS = (long long)SEQ * SEQ;
    const int HM = BSX / 2;

    cudaFuncSetAttribute((const void*)flash_k, cudaFuncAttributeMaxDynamicSharedMemorySize, FS_TOT_BYTES);
    cudaFuncSetAttribute((const void*)hgemm<0, 0, 0, 0, 0>, cudaFuncAttributeMaxDynamicSharedMemorySize, HG_SMEM);
    cudaFuncSetAttribute((const void*)hgemm<0, 1, 0, 0, 1>, cudaFuncAttributeMaxDynamicSharedMemorySize, HG_SMEM);
    cudaFuncSetAttribute((const void*)hgemm<0, 1, 0, 0, 0>, cudaFuncAttributeMaxDynamicSharedMemorySize, HG_SMEM);
    cudaFuncSetAttribute((const void*)hgemm<1, 1, 0, 0, 0>, cudaFuncAttributeMaxDynamicSharedMemorySize, HG_SMEM);
    cudaFuncSetAttribute((const void*)hgemm<2, 1, 0, 0, 0>, cudaFuncAttributeMaxDynamicSharedMemorySize, HG_SMEM);
    cudaFuncSetAttribute((const void*)hgemm<3, 1, 1, 1, 0>, cudaFuncAttributeMaxDynamicSharedMemorySize, HG_SMEM);

    // ---- streams/events ----
    static cudaStream_t st1 = nullptr, st2 = nullptr, st3 = nullptr;
    static cudaEvent_t e_fork, e_ln0, e_ln1, e_b1, e_w2, e_qw, e_topo, e_fl1, e_t1, e_kA, e_d0;
    if (!st1) {
        cudaStreamCreateWithFlags(&st1, cudaStreamNonBlocking);
        cudaStreamCreateWithFlags(&st2, cudaStreamNonBlocking);
        cudaStreamCreateWithFlags(&st3, cudaStreamNonBlocking);
        cudaEventCreateWithFlags(&e_fork, cudaEventDisableTiming);
        cudaEventCreateWithFlags(&e_ln0,  cudaEventDisableTiming);
        cudaEventCreateWithFlags(&e_ln1,  cudaEventDisableTiming);
        cudaEventCreateWithFlags(&e_b1,   cudaEventDisableTiming);
        cudaEventCreateWithFlags(&e_w2,   cudaEventDisableTiming);
        cudaEventCreateWithFlags(&e_qw,   cudaEventDisableTiming);
        cudaEventCreateWithFlags(&e_topo, cudaEventDisableTiming);
        cudaEventCreateWithFlags(&e_fl1,  cudaEventDisableTiming);
        cudaEventCreateWithFlags(&e_t1,   cudaEventDisableTiming);
        cudaEventCreateWithFlags(&e_kA,   cudaEventDisableTiming);
        cudaEventCreateWithFlags(&e_d0,   cudaEventDisableTiming);
    }

    dim3 tb(32, 8);

    // ---- fork ----
    cudaEventRecord(e_fork, 0);
    cudaStreamWaitEvent(st1, e_fork, 0);
    cudaStreamWaitEvent(st2, e_fork, 0);
    cudaStreamWaitEvent(st3, e_fork, 0);

    // ---- s0: l2ln batch 1 first (unblocks st2), then batch 0 ----
    l2ln_k<<<HM, 256>>>(h, ln1_s, ln1_b, HM);
    cudaEventRecord(e_ln1, 0);
    l2ln_k<<<HM, 256>>>(h, ln1_s, ln1_b, 0);
    cudaEventRecord(e_ln0, 0);

    // ---- st2: qkv transposes, then batch-1 attention chain ----
    wt_k<<<dim3(EMB / 32, EMB / 32), tb, 0, st2>>>(Wq, wt_qkv, EMB, EMB);
    wt_k<<<dim3(EMB / 32, EMB / 32), tb, 0, st2>>>(Wk, wt_qkv + (long long)EMB * EMB, EMB, EMB);
    wt_k<<<dim3(EMB / 32, EMB / 32), tb, 0, st2>>>(Wv, wt_qkv + 2LL * EMB * EMB, EMB, EMB);
    cudaEventRecord(e_qw, st2);
    cudaStreamWaitEvent(st2, e_ln1, 0);
    hgemm<0, 1, 0, 0, 0><<<dim3(QKVW / 128, HM / 128, 1), 256, HG_SMEM, st2>>>(
        xh + (long long)HM * EMB, wt_qkv, qkvh + (long long)HM * QKVW, nullptr, nullptr, nullptr,
        EMB, EMB, EMB, QKVW, 0, 0, 1, 0, 0, 0, 0, 0, 0);
    flash_k<<<dim3(16, NH), 256, FS_TOT_BYTES, st2>>>(qkvh, mask, cath, NH);
    cudaEventRecord(e_fl1, st2);

    // ---- st3: tail transposes + topo proj + knn(b0) ----
    wt_k<<<dim3(EMB / 32, CATW / 32), tb, 0, st3>>>(W_gate, wt_gate, CATW, EMB);
    wt_k<<<dim3(EMB / 32, EMB / 32),  tb, 0, st3>>>(W_o, wt_o, EMB, EMB);
    wt_k<<<dim3(FF / 32, EMB / 32),   tb, 0, st3>>>(W_f1, wt_f1, EMB, FF);
    wt_k<<<dim3(EMB / 32, FF / 32),   tb, 0, st3>>>(W_f2, wt_f2, FF, EMB);
    cudaEventRecord(e_w2, st3);
    wt_k<<<dim3(TT / 32, EMB / 32), tb, 0, st3>>>(W_topo, wt_topo, EMB, TT);
    cudaStreamWaitEvent(st3, e_ln0, 0);
    hgemm<0, 0, 0, 0, 0><<<dim3(1, 32, 1), 256, HG_SMEM, st3>>>(hh, wt_topo, topo, b_topo, nullptr, nullptr,
        EMB, EMB, EMB, TT, 0, 0, 1, 0, 0, 0, 0, 0, 0);
    cudaEventRecord(e_topo, st3);

    // ---- st1: topo-MLP transposes, then symmetric fp16 dist per batch ----
    wt_k<<<dim3(256 / 32, TT / 32), tb, 0, st1>>>(W_m1, wt_m1, TT, 256);
    wt_k<<<dim3(TT / 32, 256 / 32), tb, 0, st1>>>(W_m2, wt_m2, 256, TT);
    wt_k<<<dim3(TT / 32, TT / 32),  tb, 0, st1>>>(W_p1, wt_p1, TT, TT);
    wt_k<<<dim3(TT / 32, TT / 32),  tb, 0, st1>>>(W_p2, wt_p2, TT, TT);
    cudaStreamWaitEvent(st1, e_ln0, 0);
    hgemm<0, 1, 0, 0, 1><<<dim3(16, 16, 1), 256, HG_SMEM, st1>>>(
        hnh, hnh, disth, nullptr, nullptr, nullptr,
        EMB, EMB, EMB, SEQ, 0, 0, 1, 0, 0, 0, 0, 0, 0);
    cudaEventRecord(e_d0, st1);
    hgemm<0, 1, 0, 0, 1><<<dim3(16, 16, 1), 256, HG_SMEM, st1>>>(
        hnh + SE, hnh + SE, disth + SS, nullptr, nullptr, nullptr,
        EMB, EMB, EMB, SEQ, 0, 0, 1, 0, 0, 0, 0, 0, 0);
    cudaStreamWaitEvent(st3, e_topo, 0);
    cudaStreamWaitEvent(st3, e_d0, 0);
    knn_k<<<SEQ, 256, 0, st3>>>(0);
    cudaEventRecord(e_kA, st3);
    cudaStreamWaitEvent(st1, e_topo, 0);
    knn_k<<<SEQ, 256, 0, st1>>>(SEQ);
    cudaStreamWaitEvent(st1, e_kA, 0);

    // ---- st1: topo MLP chain ----
    hgemm<1, 1, 0, 0, 0><<<dim3(2, 32, 1), 256, HG_SMEM, st1>>>(combh, wt_m1, tmp256h, b_m1, nullptr, nullptr,
        TT, TT, TT, 256, 0, 0, 1, 0, 0, 0, 0, 0, 0);
    hgemm<0, 0, 0, 0, 0><<<dim3(1, 32, 1), 256, HG_SMEM, st1>>>(tmp256h, wt_m2, tt, b_m2, nullptr, nullptr,
        256, 256, 256, TT, 0, 0, 1, 0, 0, 0, 0, 0, 0);
    lnh_k<128, 1><<<BSX, 128, 0, st1>>>(tt, tth, ln_t_s, ln_t_b, TT);
    hgemm<1, 1, 0, 0, 0><<<dim3(1, 32, 1), 256, HG_SMEM, st1>>>(tth, wt_p1, tmp256h, b_p1, nullptr, nullptr,
        TT, TT, TT, TT, 0, 0, 1, 0, 0, 0, 0, 0, 0);
    hgemm<0, 1, 0, 0, 0><<<dim3(1, 32, 1), 256, HG_SMEM, st1>>>(tmp256h, wt_p2, cath + EMB, b_p2, nullptr, nullptr,
        TT, TT, TT, CATW, 0, 0, 1, 0, 0, 0, 0, 0, 0);
    cudaEventRecord(e_b1, st1);

    // ---- s0: batch-0 attention chain ----
    cudaStreamWaitEvent(0, e_qw, 0);
    hgemm<0, 1, 0, 0, 0><<<dim3(QKVW / 128, HM / 128, 1), 256, HG_SMEM>>>(xh, wt_qkv, qkvh, nullptr, nullptr, nullptr,
        EMB, EMB, EMB, QKVW, 0, 0, 1, 0, 0, 0, 0, 0, 0);
    flash_k<<<dim3(16, NH), 256, FS_TOT_BYTES>>>(qkvh, mask, cath, 0);

    // ---- tail half 0 on s0 ----
    cudaStreamWaitEvent(0, e_b1, 0);
    cudaStreamWaitEvent(0, e_w2, 0);
    hgemm<3, 1, 1, 1, 0><<<dim3(6, HM / 128, 1), 256, HG_SMEM>>>(cath, wt_gate, ctxh, b_gate, cath, xh,
        CATW, CATW, CATW, EMB, CATW, EMB, 1, 0, 0, 0, 0, 0, 0);
    hgemm<0, 0, 0, 0, 0><<<dim3(6, HM / 128, 1), 256, HG_SMEM>>>(ctxh, wt_o, h1, b_o, h, nullptr,
        EMB, EMB, EMB, EMB, EMB, 0, 1, 0, 0, 0, 0, 0, 0);
    lnh_k<256, 3><<<HM, 256>>>(h1, yh, ln2_s, ln2_b, EMB);
    hgemm<2, 1, 0, 0, 0><<<dim3(24, HM / 128, 1), 256, HG_SMEM>>>(yh, wt_f1, ffh, b_f1, nullptr, nullptr,
        EMB, EMB, EMB, FF, 0, 0, 1, 0, 0, 0, 0, 0, 0);
    hgemm<0, 0, 0, 0, 0><<<dim3(6, HM / 128, 1), 256, HG_SMEM>>>(ffh, wt_f2, out, b_f2, h1, nullptr,
        FF, FF, FF, EMB, EMB, 0, 1, 0, 0, 0, 0, 0, 0);

    // ---- tail half 1 on st1 ----
    cudaStreamWaitEvent(st1, e_fl1, 0);
    cudaStreamWaitEvent(st1, e_w2, 0);
    {
        const long long rO = (long long)HM;
        hgemm<3, 1, 1, 1, 0><<<dim3(6, HM / 128, 1), 256, HG_SMEM, st1>>>(
            cath + rO * CATW, wt_gate, ctxh + rO * EMB, b_gate,
            cath + rO * CATW, xh + rO * EMB,
            CATW, CATW, CATW, EMB, CATW, EMB, 1, 0, 0, 0, 0, 0, 0);
        hgemm<0, 0, 0, 0, 0><<<dim3(6, HM / 128, 1), 256, HG_SMEM, st1>>>(
            ctxh + rO * EMB, wt_o, h1 + rO * EMB, b_o, h + rO * EMB, nullptr,
            EMB, EMB, EMB, EMB, EMB, 0, 1, 0, 0, 0, 0, 0, 0);
        lnh_k<256, 3><<<HM, 256, 0, st1>>>(h1 + rO * EMB, yh + rO * EMB, ln2_s, ln2_b, EMB);
        hgemm<2, 1, 0, 0, 0><<<dim3(24, HM / 128, 1), 256, HG_SMEM, st1>>>(
            yh + rO * EMB, wt_f1, ffh + rO * FF, b_f1, nullptr, nullptr,
            EMB, EMB, EMB, FF, 0, 0, 1, 0, 0, 0, 0, 0, 0);
        hgemm<0, 0, 0, 0, 0><<<dim3(6, HM / 128, 1), 256, HG_SMEM, st1>>>(
            ffh + rO * FF, wt_f2, out + rO * EMB, b_f2, h1 + rO * EMB, nullptr,
            FF, FF, FF, EMB, EMB, 0, 1, 0, 0, 0, 0, 0, 0);
        cudaEventRecord(e_t1, st1);
    }
    cudaStreamWaitEvent(0, e_t1, 0);
}